// round 9
// baseline (speedup 1.0000x reference)
#include <cuda_runtime.h>
#include <math.h>
#include <stdint.h>

// VIN via backward-cone pyramids: 64 independent CTAs (no cluster, no
// cross-CTA sync), one per query point. Each CTA computes r/qr over the
// query's 19-step dependence cone (<=41x41) in its own SMEM, then 18
// shrinking value-iteration sweeps (hw=18..1), then q+softmax at its point.
// fma.rn.f32x2 computes 2 adjacent cells per task; the 8 actions are split
// across even/odd lanes (36 packed weight regs each -> fully register
// resident) and combined with one shfl.xor. Only batch 0 reaches the output;
// the 150-ch hidden conv collapses into a 2-ch 3x3 effective conv.
// FIX vs prev round: rB is forced to 0 at out-of-grid cells (the reference
// zero-pads r outside the grid; the bias term must NOT leak into ghost cells).

#define NACT 8
#define NTH 448               // 14 warps
#define ST 44                 // buffer row stride (floats)
#define BR 43                 // buffer rows/cols (0..42), query at (21,21)
#define NPAIR 20              // column pairs: pair p covers cols (2p+1, 2p+2)

// dynamic smem layout (bytes)
#define QR2_U64   (NACT * BR * NPAIR)            // 6880 u64
#define OFF_QR2   0
#define OFF_F     (QR2_U64 * 8)                  // float region starts here
#define F_XS      0                              // [2][43][44]
#define F_RB      (F_XS + 2 * BR * ST)
#define F_VA      (F_RB + BR * ST)
#define F_VB      (F_VA + BR * ST)
#define F_WQS     (F_VB + BR * ST)               // raw Wq, 144
#define F_PART    (F_WQS + 144)                  // 19*8 collapse partials
#define F_WEFF    (F_PART + 152)                 // 19
#define F_TOTAL   (F_WEFF + 19)
#define SMEM_BYTES (OFF_F + F_TOTAL * 4)

__device__ __forceinline__ uint64_t pack2(float x, float y) {
    uint64_t r;
    asm("mov.b64 %0, {%1, %2};" : "=l"(r) : "f"(x), "f"(y));
    return r;
}
__device__ __forceinline__ float2 unpack2(uint64_t v) {
    float2 f;
    asm("mov.b64 {%0, %1}, %2;" : "=f"(f.x), "=f"(f.y) : "l"(v));
    return f;
}
__device__ __forceinline__ uint64_t fma2(uint64_t a, uint64_t b, uint64_t c) {
    uint64_t d;
    asm("fma.rn.f32x2 %0, %1, %2, %3;" : "=l"(d) : "l"(a), "l"(b), "l"(c));
    return d;
}

__global__ __launch_bounds__(NTH, 1)
void vin_kernel(const float* __restrict__ X,
                const int* __restrict__ S1,
                const int* __restrict__ S2,
                const float* __restrict__ Wh,
                const float* __restrict__ bh,
                const float* __restrict__ Wr,
                const float* __restrict__ Wq,
                float* __restrict__ out)
{
    extern __shared__ char smem_raw[];
    uint64_t* qr2 = (uint64_t*)(smem_raw + OFF_QR2);   // [8][43][20]
    float* fb   = (float*)(smem_raw + OFF_F);
    float* Xs   = fb + F_XS;
    float* rB   = fb + F_RB;
    float* vA   = fb + F_VA;
    float* vB   = fb + F_VB;
    float* wqs  = fb + F_WQS;
    float* part = fb + F_PART;
    float* weff = fb + F_WEFF;

    const int t = threadIdx.x;
    const int b = blockIdx.x;
    const int half = t & 1;            // even lane: actions 0-3, odd: 4-7
    const int abase = half * 4;

    const int qi = S1[b];
    const int qj = S2[b];
    const int OY = qi - 21;            // buffer (by,bx) <-> grid (OY+by, OX+bx)
    const int OX = qj - 21;

    // ---- init: zero v buffers + rB, stage Wq, weight-collapse partials ----
    for (int i = t; i < BR * ST; i += NTH) { vA[i] = 0.f; vB[i] = 0.f; rB[i] = 0.f; }
    if (t < 144) wqs[t] = Wq[t];
    if (t < 152) {
        int p = t >> 3, c = t & 7;
        float s = 0.f;
        for (int h = c; h < 150; h += 8)
            s += Wr[h] * (p < 18 ? Wh[h * 18 + p] : bh[h]);
        part[p * 8 + c] = s;
    }
    __syncthreads();
    if (t < 19) {
        float s = 0.f;
        #pragma unroll
        for (int c = 0; c < 8; c++) s += part[t * 8 + c];
        weff[t] = s;
    }

    // ---- load X cone region [43x43] x 2ch, zero-filled outside grid ----
    for (int c = 0; c < 2; c++) {
        for (int idx = t; idx < BR * BR; idx += NTH) {
            int by = (int)((idx + 0.5f) * (1.0f / 43.0f));
            int bx = idx - by * 43;
            int gy = OY + by, gx = OX + bx;
            float v = 0.f;
            if (gy >= 0 && gy < 64 && gx >= 0 && gx < 64)
                v = X[c * 4096 + gy * 64 + gx];
            Xs[c * BR * ST + by * ST + bx] = v;
        }
    }
    __syncthreads();

    // ---- reward r over IN-GRID cells of [1,41]^2; out-of-grid stays 0 ----
    // (the reference zero-pads r outside the grid: ghost cells must be 0,
    //  NOT bias + conv-of-zeros)
    {
        float we[18];
        #pragma unroll
        for (int p = 0; p < 18; p++) we[p] = weff[p];
        const float b0 = weff[18];
        for (int idx = t; idx < 41 * 41; idx += NTH) {
            int r0 = (int)((idx + 0.5f) * (1.0f / 41.0f));
            int bx = idx - r0 * 41 + 1;
            int by = r0 + 1;
            int gy = OY + by, gx = OX + bx;
            if (gy < 0 || gy >= 64 || gx < 0 || gx >= 64) continue;  // stays 0
            float acc = b0;
            #pragma unroll
            for (int c = 0; c < 2; c++)
                #pragma unroll
                for (int ky = 0; ky < 3; ky++)
                    #pragma unroll
                    for (int kx = 0; kx < 3; kx++)
                        acc = fmaf(we[c * 9 + ky * 3 + kx],
                                   Xs[c * BR * ST + (by - 1 + ky) * ST + bx - 1 + kx],
                                   acc);
            rB[by * ST + bx] = acc;
        }
    }
    __syncthreads();

    // ---- qr = conv(r, Wq[:,0]) over rows [2,40] x 20 pairs; v1 = max_a qr ----
    {
        uint64_t wr[36];       // my 4 actions' r-channel weights, packed (w,w)
        #pragma unroll
        for (int i = 0; i < 4; i++)
            #pragma unroll
            for (int p = 0; p < 9; p++) {
                float wv = wqs[(abase + i) * 18 + p];
                wr[i * 9 + p] = pack2(wv, wv);
            }
        // v1 span (hw=19, grid-clipped)
        const int byLo1 = 21 - min(19, qi), byHi1 = 21 + min(19, 63 - qi);
        const int bxLo1 = 21 - min(19, qj), bxHi1 = 21 + min(19, 63 - qj);

        const int nsub = 39 * NPAIR * 2;           // 1560
        for (int k = 0; k < (nsub + NTH - 1) / NTH; k++) {
            int u = t + k * NTH;
            bool active = (u < nsub);
            int pt = active ? (u >> 1) : 0;
            int row = (int)((pt + 0.5f) * 0.05f);  // /20
            int p = pt - row * 20;
            int by = row + 2;

            uint64_t acc[4] = {0ull, 0ull, 0ull, 0ull};
            #pragma unroll
            for (int ky = 0; ky < 3; ky++) {
                const uint64_t* rowp =
                    (const uint64_t*)(rB + (by - 1 + ky) * ST + 2 * p);
                uint64_t a01 = rowp[0], a23 = rowp[1];
                float2 f01 = unpack2(a01), f23 = unpack2(a23);
                uint64_t pm = pack2(f01.y, f23.x);
                #pragma unroll
                for (int i = 0; i < 4; i++) {
                    acc[i] = fma2(wr[i * 9 + ky * 3 + 0], a01, acc[i]);
                    acc[i] = fma2(wr[i * 9 + ky * 3 + 1], pm,  acc[i]);
                    acc[i] = fma2(wr[i * 9 + ky * 3 + 2], a23, acc[i]);
                }
            }
            float v0 = -INFINITY, v1 = -INFINITY;
            #pragma unroll
            for (int i = 0; i < 4; i++) {
                if (active)
                    qr2[((abase + i) * BR + by) * NPAIR + p] = acc[i];
                float2 f = unpack2(acc[i]);
                v0 = fmaxf(v0, f.x);
                v1 = fmaxf(v1, f.y);
            }
            v0 = fmaxf(v0, __shfl_xor_sync(0xffffffffu, v0, 1));
            v1 = fmaxf(v1, __shfl_xor_sync(0xffffffffu, v1, 1));
            if (active && by >= byLo1 && by <= byHi1) {
                int c0 = 2 * p + 1;
                if (half == 0) {
                    if (c0 >= bxLo1 && c0 <= bxHi1) vA[by * ST + c0] = v0;
                } else {
                    if (c0 + 1 >= bxLo1 && c0 + 1 <= bxHi1) vA[by * ST + c0 + 1] = v1;
                }
            }
        }
    }

    // my 4 actions' v-channel weights, packed, register-resident for the loop
    uint64_t wp[36];
    #pragma unroll
    for (int i = 0; i < 4; i++)
        #pragma unroll
        for (int p = 0; p < 9; p++) {
            float wv = wqs[(abase + i) * 18 + 9 + p];
            wp[i * 9 + p] = pack2(wv, wv);
        }
    __syncthreads();

    // ---- 18 shrinking sweeps: v2..v19 (hw = 18..1) ----
    float* cur = vA;
    float* nxt = vB;
    for (int s = 2; s <= 19; s++) {
        const int hw = 20 - s;
        const int byLo = 21 - min(hw, qi), byHi = 21 + min(hw, 63 - qi);
        const int bxLo = 21 - min(hw, qj), bxHi = 21 + min(hw, 63 - qj);
        const int p0 = (bxLo - 1) >> 1, p1 = (bxHi - 1) >> 1;
        const int np = p1 - p0 + 1;
        const int nr = byHi - byLo + 1;
        const int nsub = nr * np * 2;
        const float invnp = 1.0f / (float)np;
        const int passes = (nsub + NTH - 1) / NTH;

        for (int k = 0; k < passes; k++) {
            int u = t + k * NTH;
            bool active = (u < nsub);
            int pt = active ? (u >> 1) : 0;
            int row = (int)((pt + 0.5f) * invnp);
            int p = p0 + pt - row * np;
            int by = byLo + row;

            uint64_t acc[4];
            #pragma unroll
            for (int i = 0; i < 4; i++)
                acc[i] = qr2[((abase + i) * BR + by) * NPAIR + p];

            #pragma unroll
            for (int ky = 0; ky < 3; ky++) {
                const uint64_t* rowp =
                    (const uint64_t*)(cur + (by - 1 + ky) * ST + 2 * p);
                uint64_t a01 = rowp[0], a23 = rowp[1];
                float2 f01 = unpack2(a01), f23 = unpack2(a23);
                uint64_t pm = pack2(f01.y, f23.x);
                #pragma unroll
                for (int i = 0; i < 4; i++) {
                    acc[i] = fma2(wp[i * 9 + ky * 3 + 0], a01, acc[i]);
                    acc[i] = fma2(wp[i * 9 + ky * 3 + 1], pm,  acc[i]);
                    acc[i] = fma2(wp[i * 9 + ky * 3 + 2], a23, acc[i]);
                }
            }
            float v0 = -INFINITY, v1 = -INFINITY;
            #pragma unroll
            for (int i = 0; i < 4; i++) {
                float2 f = unpack2(acc[i]);
                v0 = fmaxf(v0, f.x);
                v1 = fmaxf(v1, f.y);
            }
            v0 = fmaxf(v0, __shfl_xor_sync(0xffffffffu, v0, 1));
            v1 = fmaxf(v1, __shfl_xor_sync(0xffffffffu, v1, 1));
            if (active) {
                int c0 = 2 * p + 1;
                if (half == 0) {
                    if (c0 >= bxLo && c0 <= bxHi) nxt[by * ST + c0] = v0;
                } else {
                    if (c0 + 1 >= bxLo && c0 + 1 <= bxHi) nxt[by * ST + c0 + 1] = v1;
                }
            }
        }
        __syncthreads();
        float* tmp = cur; cur = nxt; nxt = tmp;
    }

    // ---- final: q at (21,21) from v19 + qr, softmax, write own out row ----
    if (t == 0) {
        float q[NACT];
        float m = -INFINITY;
        #pragma unroll
        for (int a = 0; a < NACT; a++) {
            float2 f = unpack2(qr2[(a * BR + 21) * NPAIR + 10]);  // cell bc=21
            float acc = f.x;
            #pragma unroll
            for (int ky = 0; ky < 3; ky++)
                #pragma unroll
                for (int kx = 0; kx < 3; kx++)
                    acc = fmaf(wqs[a * 18 + 9 + ky * 3 + kx],
                               cur[(20 + ky) * ST + 20 + kx], acc);
            q[a] = acc;
            m = fmaxf(m, acc);
        }
        float s = 0.f;
        #pragma unroll
        for (int a = 0; a < NACT; a++) { q[a] = expf(q[a] - m); s += q[a]; }
        float inv = 1.f / s;
        #pragma unroll
        for (int a = 0; a < NACT; a++)
            out[b * NACT + a] = q[a] * inv;
    }
}

extern "C" void kernel_launch(void* const* d_in, const int* in_sizes, int n_in,
                              void* d_out, int out_size)
{
    const float* X  = (const float*)d_in[0];   // [64,2,64,64] (batch 0 only)
    const int*   S1 = (const int*)d_in[1];     // [64]
    const int*   S2 = (const int*)d_in[2];     // [64]
    const float* Wh = (const float*)d_in[3];   // [150,2,3,3]
    const float* bh = (const float*)d_in[4];   // [150]
    const float* Wr = (const float*)d_in[5];   // [1,150,1,1]
    const float* Wq = (const float*)d_in[6];   // [8,2,3,3]
    float* out = (float*)d_out;                // [64,8]

    cudaFuncSetAttribute(vin_kernel,
                         cudaFuncAttributeMaxDynamicSharedMemorySize,
                         SMEM_BYTES);
    vin_kernel<<<64, NTH, SMEM_BYTES>>>(X, S1, S2, Wh, bh, Wr, Wq, out);
}

// round 10
// speedup vs baseline: 1.1004x; 1.1004x over previous
#include <cuda_runtime.h>
#include <math.h>
#include <stdint.h>

// VIN via backward-cone pyramids: 64 independent CTAs, one per query point.
// This round: piecewise-STATIC shrink (3 fixed regions, 6 sweeps each), with
// per-thread task descriptors (addresses + write predicate) precomputed in
// registers before each phase, so the sweep bodies contain no index math.
// Correctness of fixed regions: edge errors move inward 1 cell/sweep, always
// one cell behind the shrinking required-correct radius (20-s).
// fma.rn.f32x2 computes 2 adjacent cells; 8 actions split across even/odd
// lanes (36 packed weight regs) and combined with one shfl.xor.

#define NACT 8
#define NTH 448               // 14 warps
#define ST 44                 // buffer row stride (floats)
#define BR 43                 // buffer rows/cols (0..42), query at (21,21)
#define NPAIR 20              // column pairs: pair p covers cols (2p+1, 2p+2)
#define VSZ (BR * ST)

// dynamic smem layout (bytes)
#define QR2_U64   (NACT * BR * NPAIR)            // 6880 u64
#define OFF_QR2   0
#define OFF_F     (QR2_U64 * 8)
#define F_XS      0                              // [2][43][44]
#define F_RB      (F_XS + 2 * VSZ)
#define F_VA      (F_RB + VSZ)                   // vA, vB contiguous
#define F_VB      (F_VA + VSZ)
#define F_WQS     (F_VB + VSZ)                   // raw Wq, 144
#define F_PART    (F_WQS + 144)                  // 19*8 collapse partials
#define F_WEFF    (F_PART + 152)                 // 19
#define F_TOTAL   (F_WEFF + 19)
#define SMEM_BYTES (OFF_F + F_TOTAL * 4)

__device__ __forceinline__ uint64_t pack2(float x, float y) {
    uint64_t r;
    asm("mov.b64 %0, {%1, %2};" : "=l"(r) : "f"(x), "f"(y));
    return r;
}
__device__ __forceinline__ float2 unpack2(uint64_t v) {
    float2 f;
    asm("mov.b64 {%0, %1}, %2;" : "=f"(f.x), "=f"(f.y) : "l"(v));
    return f;
}
__device__ __forceinline__ uint64_t fma2(uint64_t a, uint64_t b, uint64_t c) {
    uint64_t d;
    asm("fma.rn.f32x2 %0, %1, %2, %3;" : "=l"(d) : "l"(a), "l"(b), "l"(c));
    return d;
}

// One VI phase: NSW identical sweeps over a fixed region of NROWS rows
// (starting ROW0) x NPRS pairs (starting PAIR0), NPASS passes per sweep.
// All task geometry is computed ONCE into registers before the sweep loop.
#define RUN_PHASE(NSW, NPASS, NROWS, NPRS, ROW0, PAIR0)                       \
{                                                                             \
    unsigned qoff[NPASS]; int roff[NPASS]; int soff[NPASS]; bool wr[NPASS];   \
    _Pragma("unroll")                                                         \
    for (int k = 0; k < NPASS; k++) {                                         \
        int u = t + k * NTH;                                                  \
        bool act = (u < (NROWS) * (NPRS) * 2);                                \
        int pt = act ? (u >> 1) : 0;                                          \
        int row = pt / (NPRS);                                                \
        int p = pt - row * (NPRS) + (PAIR0);                                  \
        int by = row + (ROW0);                                                \
        int c = 2 * p + 1 + half;                                             \
        qoff[k] = (unsigned)((abase * BR + by) * NPAIR + p);                  \
        roff[k] = (by - 1) * ST + 2 * p;                                      \
        soff[k] = by * ST + c;                                                \
        int gy = OY + by, gx = OX + c;                                        \
        wr[k] = act && gy >= 0 && gy < 64 && gx >= 0 && gx < 64;              \
    }                                                                         \
    for (int s = 0; s < (NSW); s++) {                                         \
        const float* cur = vbase + parity * VSZ;                              \
        float* nxt = vbase + (parity ^ 1) * VSZ;                              \
        _Pragma("unroll")                                                     \
        for (int k = 0; k < NPASS; k++) {                                     \
            uint64_t a0 = qr2[qoff[k]];                                       \
            uint64_t a1 = qr2[qoff[k] + BR * NPAIR];                          \
            uint64_t a2 = qr2[qoff[k] + 2 * BR * NPAIR];                      \
            uint64_t a3 = qr2[qoff[k] + 3 * BR * NPAIR];                      \
            _Pragma("unroll")                                                 \
            for (int ky = 0; ky < 3; ky++) {                                  \
                const uint64_t* rowp =                                        \
                    (const uint64_t*)(cur + roff[k] + ky * ST);               \
                uint64_t a01 = rowp[0], a23 = rowp[1];                        \
                float2 f01 = unpack2(a01), f23 = unpack2(a23);                \
                uint64_t pm = pack2(f01.y, f23.x);                            \
                a0 = fma2(wp[0 * 9 + ky * 3 + 0], a01, a0);                   \
                a0 = fma2(wp[0 * 9 + ky * 3 + 1], pm,  a0);                   \
                a0 = fma2(wp[0 * 9 + ky * 3 + 2], a23, a0);                   \
                a1 = fma2(wp[1 * 9 + ky * 3 + 0], a01, a1);                   \
                a1 = fma2(wp[1 * 9 + ky * 3 + 1], pm,  a1);                   \
                a1 = fma2(wp[1 * 9 + ky * 3 + 2], a23, a1);                   \
                a2 = fma2(wp[2 * 9 + ky * 3 + 0], a01, a2);                   \
                a2 = fma2(wp[2 * 9 + ky * 3 + 1], pm,  a2);                   \
                a2 = fma2(wp[2 * 9 + ky * 3 + 2], a23, a2);                   \
                a3 = fma2(wp[3 * 9 + ky * 3 + 0], a01, a3);                   \
                a3 = fma2(wp[3 * 9 + ky * 3 + 1], pm,  a3);                   \
                a3 = fma2(wp[3 * 9 + ky * 3 + 2], a23, a3);                   \
            }                                                                 \
            float2 f0 = unpack2(a0), f1 = unpack2(a1);                        \
            float2 f2 = unpack2(a2), f3 = unpack2(a3);                        \
            float v0 = fmaxf(fmaxf(f0.x, f1.x), fmaxf(f2.x, f3.x));           \
            float v1 = fmaxf(fmaxf(f0.y, f1.y), fmaxf(f2.y, f3.y));           \
            v0 = fmaxf(v0, __shfl_xor_sync(0xffffffffu, v0, 1));              \
            v1 = fmaxf(v1, __shfl_xor_sync(0xffffffffu, v1, 1));              \
            if (wr[k]) nxt[soff[k]] = half ? v1 : v0;                         \
        }                                                                     \
        __syncthreads();                                                      \
        parity ^= 1;                                                          \
    }                                                                         \
}

__global__ __launch_bounds__(NTH, 1)
void vin_kernel(const float* __restrict__ X,
                const int* __restrict__ S1,
                const int* __restrict__ S2,
                const float* __restrict__ Wh,
                const float* __restrict__ bh,
                const float* __restrict__ Wr,
                const float* __restrict__ Wq,
                float* __restrict__ out)
{
    extern __shared__ char smem_raw[];
    uint64_t* qr2 = (uint64_t*)(smem_raw + OFF_QR2);   // [8][43][20]
    float* fb   = (float*)(smem_raw + OFF_F);
    float* Xs   = fb + F_XS;
    float* rB   = fb + F_RB;
    float* vbase = fb + F_VA;                          // vA then vB
    float* vA   = vbase;
    float* wqs  = fb + F_WQS;
    float* part = fb + F_PART;
    float* weff = fb + F_WEFF;

    const int t = threadIdx.x;
    const int b = blockIdx.x;
    const int half = t & 1;            // even lane: actions 0-3, odd: 4-7
    const int abase = half * 4;

    const int qi = S1[b];
    const int qj = S2[b];
    const int OY = qi - 21;
    const int OX = qj - 21;

    // ---- init: zero v buffers + rB, stage Wq, weight-collapse partials ----
    for (int i = t; i < VSZ; i += NTH) { vA[i] = 0.f; vA[VSZ + i] = 0.f; rB[i] = 0.f; }
    if (t < 144) wqs[t] = Wq[t];
    if (t < 152) {
        int p = t >> 3, c = t & 7;
        float s = 0.f;
        for (int h = c; h < 150; h += 8)
            s += Wr[h] * (p < 18 ? Wh[h * 18 + p] : bh[h]);
        part[p * 8 + c] = s;
    }
    __syncthreads();
    if (t < 19) {
        float s = 0.f;
        #pragma unroll
        for (int c = 0; c < 8; c++) s += part[t * 8 + c];
        weff[t] = s;
    }

    // ---- load X cone region [43x43] x 2ch, zero-filled outside grid ----
    for (int c = 0; c < 2; c++) {
        for (int idx = t; idx < BR * BR; idx += NTH) {
            int by = (int)((idx + 0.5f) * (1.0f / 43.0f));
            int bx = idx - by * 43;
            int gy = OY + by, gx = OX + bx;
            float v = 0.f;
            if (gy >= 0 && gy < 64 && gx >= 0 && gx < 64)
                v = X[c * 4096 + gy * 64 + gx];
            Xs[c * VSZ + by * ST + bx] = v;
        }
    }
    __syncthreads();

    // ---- reward r over IN-GRID cells of [1,41]^2; out-of-grid stays 0 ----
    {
        float we[18];
        #pragma unroll
        for (int p = 0; p < 18; p++) we[p] = weff[p];
        const float b0 = weff[18];
        for (int idx = t; idx < 41 * 41; idx += NTH) {
            int r0 = (int)((idx + 0.5f) * (1.0f / 41.0f));
            int bx = idx - r0 * 41 + 1;
            int by = r0 + 1;
            int gy = OY + by, gx = OX + bx;
            if (gy < 0 || gy >= 64 || gx < 0 || gx >= 64) continue;
            float acc = b0;
            #pragma unroll
            for (int c = 0; c < 2; c++)
                #pragma unroll
                for (int ky = 0; ky < 3; ky++)
                    #pragma unroll
                    for (int kx = 0; kx < 3; kx++)
                        acc = fmaf(we[c * 9 + ky * 3 + kx],
                                   Xs[c * VSZ + (by - 1 + ky) * ST + bx - 1 + kx],
                                   acc);
            rB[by * ST + bx] = acc;
        }
    }
    __syncthreads();

    // ---- qr = conv(r, Wq[:,0]) rows [2,40] x pairs [0,19]; v1 = max_a qr ----
    {
        uint64_t wr9[36];
        #pragma unroll
        for (int i = 0; i < 4; i++)
            #pragma unroll
            for (int p = 0; p < 9; p++) {
                float wv = wqs[(abase + i) * 18 + p];
                wr9[i * 9 + p] = pack2(wv, wv);
            }
        const int nsub = 39 * NPAIR * 2;               // 1560
        #pragma unroll
        for (int k = 0; k < 4; k++) {
            int u = t + k * NTH;
            bool active = (u < nsub);
            int pt = active ? (u >> 1) : 0;
            int row = pt / NPAIR;
            int p = pt - row * NPAIR;
            int by = row + 2;

            uint64_t acc[4] = {0ull, 0ull, 0ull, 0ull};
            #pragma unroll
            for (int ky = 0; ky < 3; ky++) {
                const uint64_t* rowp =
                    (const uint64_t*)(rB + (by - 1 + ky) * ST + 2 * p);
                uint64_t a01 = rowp[0], a23 = rowp[1];
                float2 f01 = unpack2(a01), f23 = unpack2(a23);
                uint64_t pm = pack2(f01.y, f23.x);
                #pragma unroll
                for (int i = 0; i < 4; i++) {
                    acc[i] = fma2(wr9[i * 9 + ky * 3 + 0], a01, acc[i]);
                    acc[i] = fma2(wr9[i * 9 + ky * 3 + 1], pm,  acc[i]);
                    acc[i] = fma2(wr9[i * 9 + ky * 3 + 2], a23, acc[i]);
                }
            }
            float v0 = -INFINITY, v1 = -INFINITY;
            #pragma unroll
            for (int i = 0; i < 4; i++) {
                if (active)
                    qr2[((abase + i) * BR + by) * NPAIR + p] = acc[i];
                float2 f = unpack2(acc[i]);
                v0 = fmaxf(v0, f.x);
                v1 = fmaxf(v1, f.y);
            }
            v0 = fmaxf(v0, __shfl_xor_sync(0xffffffffu, v0, 1));
            v1 = fmaxf(v1, __shfl_xor_sync(0xffffffffu, v1, 1));
            // v1 span: cols [2,40] (col 1 excluded), rows [2,40], in-grid
            int c = 2 * p + 1 + half;
            int gy = OY + by, gx = OX + c;
            if (active && c >= 2 &&
                gy >= 0 && gy < 64 && gx >= 0 && gx < 64)
                vA[by * ST + c] = half ? v1 : v0;
        }
    }

    // my 4 actions' v-channel weights, packed, register-resident for the loop
    uint64_t wp[36];
    #pragma unroll
    for (int i = 0; i < 4; i++)
        #pragma unroll
        for (int p = 0; p < 9; p++) {
            float wv = wqs[(abase + i) * 18 + 9 + p];
            wp[i * 9 + p] = pack2(wv, wv);
        }
    __syncthreads();

    // ---- 18 sweeps: 3 phases of 6 with fixed regions ----
    int parity = 0;
    RUN_PHASE(6, 4, 39, 19, 2, 1);     // s=2..7:   rows 2..40, pairs 1..19
    RUN_PHASE(6, 2, 27, 14, 8, 3);     // s=8..13:  rows 8..34, pairs 3..16
    RUN_PHASE(6, 1, 15,  8, 14, 6);    // s=14..19: rows 14..28, pairs 6..13
    // parity flipped 18 times -> v19 lives in vA (parity back to 0)

    // ---- final: q at (21,21) from v19 + qr, softmax, write own out row ----
    if (t == 0) {
        const float* cur = vbase;      // parity == 0
        float q[NACT];
        float m = -INFINITY;
        #pragma unroll
        for (int a = 0; a < NACT; a++) {
            float2 f = unpack2(qr2[(a * BR + 21) * NPAIR + 10]);  // cell (21,21)
            float acc = f.x;
            #pragma unroll
            for (int ky = 0; ky < 3; ky++)
                #pragma unroll
                for (int kx = 0; kx < 3; kx++)
                    acc = fmaf(wqs[a * 18 + 9 + ky * 3 + kx],
                               cur[(20 + ky) * ST + 20 + kx], acc);
            q[a] = acc;
            m = fmaxf(m, acc);
        }
        float s = 0.f;
        #pragma unroll
        for (int a = 0; a < NACT; a++) { q[a] = expf(q[a] - m); s += q[a]; }
        float inv = 1.f / s;
        #pragma unroll
        for (int a = 0; a < NACT; a++)
            out[b * NACT + a] = q[a] * inv;
    }
}

extern "C" void kernel_launch(void* const* d_in, const int* in_sizes, int n_in,
                              void* d_out, int out_size)
{
    const float* X  = (const float*)d_in[0];   // [64,2,64,64] (batch 0 only)
    const int*   S1 = (const int*)d_in[1];     // [64]
    const int*   S2 = (const int*)d_in[2];     // [64]
    const float* Wh = (const float*)d_in[3];   // [150,2,3,3]
    const float* bh = (const float*)d_in[4];   // [150]
    const float* Wr = (const float*)d_in[5];   // [1,150,1,1]
    const float* Wq = (const float*)d_in[6];   // [8,2,3,3]
    float* out = (float*)d_out;                // [64,8]

    cudaFuncSetAttribute(vin_kernel,
                         cudaFuncAttributeMaxDynamicSharedMemorySize,
                         SMEM_BYTES);
    vin_kernel<<<64, NTH, SMEM_BYTES>>>(X, S1, S2, Wh, bh, Wr, Wq, out);
}

// round 11
// speedup vs baseline: 1.1768x; 1.0694x over previous
#include <cuda_runtime.h>
#include <math.h>
#include <stdint.h>

// VIN backward-cone pyramid, 64 independent CTAs (one per query point),
// piecewise-static shrink (3 fixed regions x 6 sweeps, validated R10).
// This round: 4 lanes per cell-pair, 2 actions per lane -> only 18 packed
// weight u64 (36 regs) per thread, cheap enough for ptxas to keep resident
// (R5..R10 all silently reloaded weights from SMEM every use). 768 threads
// (6 warps/SMSP) for latency hiding. qr2 stored [sub][by][pair][2] with a
// padded sub stride so each lane reads both its actions' qr as one LDS.128.

#define NACT 8
#define NTH 768               // 24 warps
#define TPP 4                 // threads (lanes) per cell-pair task
#define TASKS_PER_PASS (NTH / TPP)   // 192
#define ST 44                 // buffer row stride (floats)
#define BR 43                 // buffer rows/cols, query at (21,21)
#define NPAIR 20              // pair p covers cols (2p+1, 2p+2)
#define VSZ (BR * ST)         // 1892
#define QSTR 1724             // u64 stride per sub-plane: BR*NPAIR*2 + 4 (bank pad)

// dynamic smem layout (bytes)
#define OFF_QR2   0
#define OFF_F     (4 * QSTR * 8)                 // float region
#define F_XS      0                              // [2][43][44]
#define F_RB      (F_XS + 2 * VSZ)
#define F_VA      (F_RB + VSZ)
#define F_VB      (F_VA + VSZ)
#define F_WQS     (F_VB + VSZ)                   // raw Wq, 144
#define F_PART    (F_WQS + 144)
#define F_WEFF    (F_PART + 152)
#define F_TOTAL   (F_WEFF + 19)
#define SMEM_BYTES (OFF_F + F_TOTAL * 4)

__device__ __forceinline__ uint64_t pack2(float x, float y) {
    uint64_t r;
    asm("mov.b64 %0, {%1, %2};" : "=l"(r) : "f"(x), "f"(y));
    return r;
}
__device__ __forceinline__ float2 unpack2(uint64_t v) {
    float2 f;
    asm("mov.b64 {%0, %1}, %2;" : "=f"(f.x), "=f"(f.y) : "l"(v));
    return f;
}
__device__ __forceinline__ uint64_t fma2(uint64_t a, uint64_t b, uint64_t c) {
    uint64_t d;
    asm("fma.rn.f32x2 %0, %1, %2, %3;" : "=l"(d) : "l"(a), "l"(b), "l"(c));
    return d;
}

// One VI phase: NSW sweeps over a fixed region (NROWS rows from ROW0,
// NPRS pairs from PAIR0), NPASS passes. Geometry precomputed in registers.
#define RUN_PHASE(NSW, NPASS, NROWS, NPRS, ROW0, PAIR0)                       \
{                                                                             \
    unsigned qoff[NPASS]; int roff[NPASS]; int soff[NPASS]; bool wr[NPASS];   \
    _Pragma("unroll")                                                         \
    for (int k = 0; k < NPASS; k++) {                                         \
        int task = (t >> 2) + k * TASKS_PER_PASS;                             \
        bool act = (task < (NROWS) * (NPRS));                                 \
        int tk = act ? task : 0;                                              \
        int row = tk / (NPRS);                                                \
        int p = tk - row * (NPRS) + (PAIR0);                                  \
        int by = row + (ROW0);                                                \
        int c = 2 * p + 1 + (sub & 1);                                        \
        qoff[k] = (unsigned)((by * NPAIR + p) * 2);                           \
        roff[k] = (by - 1) * ST + 2 * p;                                      \
        soff[k] = by * ST + c;                                                \
        int gy = OY + by, gx = OX + c;                                        \
        wr[k] = act && (sub < 2) && gy >= 0 && gy < 64 && gx >= 0 && gx < 64; \
    }                                                                         \
    for (int s = 0; s < (NSW); s++) {                                         \
        const float* cur = vbase + parity * VSZ;                              \
        float* nxt = vbase + (parity ^ 1) * VSZ;                              \
        _Pragma("unroll")                                                     \
        for (int k = 0; k < NPASS; k++) {                                     \
            ulonglong2 qq = *(const ulonglong2*)(qr2s + qoff[k]);             \
            uint64_t a0 = qq.x, a1 = qq.y;                                    \
            _Pragma("unroll")                                                 \
            for (int ky = 0; ky < 3; ky++) {                                  \
                const uint64_t* rowp =                                        \
                    (const uint64_t*)(cur + roff[k] + ky * ST);               \
                uint64_t a01 = rowp[0], a23 = rowp[1];                        \
                float2 f01 = unpack2(a01), f23 = unpack2(a23);                \
                uint64_t pm = pack2(f01.y, f23.x);                            \
                a0 = fma2(wpA[ky * 3 + 0], a01, a0);                          \
                a0 = fma2(wpA[ky * 3 + 1], pm,  a0);                          \
                a0 = fma2(wpA[ky * 3 + 2], a23, a0);                          \
                a1 = fma2(wpB[ky * 3 + 0], a01, a1);                          \
                a1 = fma2(wpB[ky * 3 + 1], pm,  a1);                          \
                a1 = fma2(wpB[ky * 3 + 2], a23, a1);                          \
            }                                                                 \
            float2 f0 = unpack2(a0), f1 = unpack2(a1);                        \
            float v0 = fmaxf(f0.x, f1.x);                                     \
            float v1 = fmaxf(f0.y, f1.y);                                     \
            v0 = fmaxf(v0, __shfl_xor_sync(0xffffffffu, v0, 1));              \
            v1 = fmaxf(v1, __shfl_xor_sync(0xffffffffu, v1, 1));              \
            v0 = fmaxf(v0, __shfl_xor_sync(0xffffffffu, v0, 2));              \
            v1 = fmaxf(v1, __shfl_xor_sync(0xffffffffu, v1, 2));              \
            if (wr[k]) nxt[soff[k]] = (sub & 1) ? v1 : v0;                    \
        }                                                                     \
        __syncthreads();                                                      \
        parity ^= 1;                                                          \
    }                                                                         \
}

__global__ __launch_bounds__(NTH, 1)
void vin_kernel(const float* __restrict__ X,
                const int* __restrict__ S1,
                const int* __restrict__ S2,
                const float* __restrict__ Wh,
                const float* __restrict__ bh,
                const float* __restrict__ Wr,
                const float* __restrict__ Wq,
                float* __restrict__ out)
{
    extern __shared__ char smem_raw[];
    uint64_t* qr2 = (uint64_t*)(smem_raw + OFF_QR2);   // [4][QSTR]
    float* fb   = (float*)(smem_raw + OFF_F);
    float* Xs   = fb + F_XS;
    float* rB   = fb + F_RB;
    float* vbase = fb + F_VA;                          // vA then vB
    float* wqs  = fb + F_WQS;
    float* part = fb + F_PART;
    float* weff = fb + F_WEFF;

    const int t = threadIdx.x;
    const int b = blockIdx.x;
    const int sub = t & 3;             // lane-in-task; actions (2*sub, 2*sub+1)
    uint64_t* qr2s = qr2 + sub * QSTR;

    const int qi = S1[b];
    const int qj = S2[b];
    const int OY = qi - 21;
    const int OX = qj - 21;

    // ---- init: zero v buffers + rB, stage Wq, weight-collapse partials ----
    for (int i = t; i < VSZ; i += NTH) {
        vbase[i] = 0.f; vbase[VSZ + i] = 0.f; rB[i] = 0.f;
    }
    if (t < 144) wqs[t] = Wq[t];
    if (t < 152) {
        int p = t >> 3, c = t & 7;
        float s = 0.f;
        for (int h = c; h < 150; h += 8)
            s += Wr[h] * (p < 18 ? Wh[h * 18 + p] : bh[h]);
        part[p * 8 + c] = s;
    }
    __syncthreads();
    if (t < 19) {
        float s = 0.f;
        #pragma unroll
        for (int c = 0; c < 8; c++) s += part[t * 8 + c];
        weff[t] = s;
    }

    // ---- load X cone region [43x43] x 2ch, zero-filled outside grid ----
    for (int c = 0; c < 2; c++) {
        for (int idx = t; idx < BR * BR; idx += NTH) {
            int by = (int)((idx + 0.5f) * (1.0f / 43.0f));
            int bx = idx - by * 43;
            int gy = OY + by, gx = OX + bx;
            float v = 0.f;
            if (gy >= 0 && gy < 64 && gx >= 0 && gx < 64)
                v = X[c * 4096 + gy * 64 + gx];
            Xs[c * VSZ + by * ST + bx] = v;
        }
    }
    __syncthreads();

    // ---- reward r over IN-GRID cells of [1,41]^2; out-of-grid stays 0 ----
    {
        float we[18];
        #pragma unroll
        for (int p = 0; p < 18; p++) we[p] = weff[p];
        const float b0 = weff[18];
        for (int idx = t; idx < 41 * 41; idx += NTH) {
            int r0 = (int)((idx + 0.5f) * (1.0f / 41.0f));
            int bx = idx - r0 * 41 + 1;
            int by = r0 + 1;
            int gy = OY + by, gx = OX + bx;
            if (gy < 0 || gy >= 64 || gx < 0 || gx >= 64) continue;
            float acc = b0;
            #pragma unroll
            for (int c = 0; c < 2; c++)
                #pragma unroll
                for (int ky = 0; ky < 3; ky++)
                    #pragma unroll
                    for (int kx = 0; kx < 3; kx++)
                        acc = fmaf(we[c * 9 + ky * 3 + kx],
                                   Xs[c * VSZ + (by - 1 + ky) * ST + bx - 1 + kx],
                                   acc);
            rB[by * ST + bx] = acc;
        }
    }
    __syncthreads();

    // ---- qr = conv(r, Wq[:,0]) rows [2,40] x pairs [0,19]; v1 = max_a qr ----
    {
        uint64_t wrA[9], wrB[9];   // my 2 actions' r-channel weights (w,w)
        #pragma unroll
        for (int p = 0; p < 9; p++) {
            float wa = wqs[(2 * sub) * 18 + p];
            float wb = wqs[(2 * sub + 1) * 18 + p];
            wrA[p] = pack2(wa, wa);
            wrB[p] = pack2(wb, wb);
        }
        const int ntask = 39 * NPAIR;              // 780
        #pragma unroll
        for (int k = 0; k < 5; k++) {
            int task = (t >> 2) + k * TASKS_PER_PASS;
            bool active = (task < ntask);
            int tk = active ? task : 0;
            int row = tk / NPAIR;
            int p = tk - row * NPAIR;
            int by = row + 2;

            uint64_t a0 = 0ull, a1 = 0ull;
            #pragma unroll
            for (int ky = 0; ky < 3; ky++) {
                const uint64_t* rowp =
                    (const uint64_t*)(rB + (by - 1 + ky) * ST + 2 * p);
                uint64_t a01 = rowp[0], a23 = rowp[1];
                float2 f01 = unpack2(a01), f23 = unpack2(a23);
                uint64_t pm = pack2(f01.y, f23.x);
                a0 = fma2(wrA[ky * 3 + 0], a01, a0);
                a0 = fma2(wrA[ky * 3 + 1], pm,  a0);
                a0 = fma2(wrA[ky * 3 + 2], a23, a0);
                a1 = fma2(wrB[ky * 3 + 0], a01, a1);
                a1 = fma2(wrB[ky * 3 + 1], pm,  a1);
                a1 = fma2(wrB[ky * 3 + 2], a23, a1);
            }
            if (active) {
                ulonglong2 qq; qq.x = a0; qq.y = a1;
                *(ulonglong2*)(qr2s + (by * NPAIR + p) * 2) = qq;
            }
            float2 f0 = unpack2(a0), f1 = unpack2(a1);
            float v0 = fmaxf(f0.x, f1.x);
            float v1 = fmaxf(f0.y, f1.y);
            v0 = fmaxf(v0, __shfl_xor_sync(0xffffffffu, v0, 1));
            v1 = fmaxf(v1, __shfl_xor_sync(0xffffffffu, v1, 1));
            v0 = fmaxf(v0, __shfl_xor_sync(0xffffffffu, v0, 2));
            v1 = fmaxf(v1, __shfl_xor_sync(0xffffffffu, v1, 2));
            // v1 span: rows [2,40], cols [2,40], in-grid; sub0->c0, sub1->c1
            int c = 2 * p + 1 + (sub & 1);
            int gy = OY + by, gx = OX + c;
            if (active && sub < 2 && c >= 2 &&
                gy >= 0 && gy < 64 && gx >= 0 && gx < 64)
                vbase[by * ST + c] = (sub & 1) ? v1 : v0;
        }
    }

    // my 2 actions' v-channel weights, packed; 18 u64 = 36 regs -> resident
    uint64_t wpA[9], wpB[9];
    #pragma unroll
    for (int p = 0; p < 9; p++) {
        float wa = wqs[(2 * sub) * 18 + 9 + p];
        float wb = wqs[(2 * sub + 1) * 18 + 9 + p];
        wpA[p] = pack2(wa, wa);
        wpB[p] = pack2(wb, wb);
    }
    __syncthreads();

    // ---- 18 sweeps: 3 fixed-region phases of 6 (validated in R10) ----
    int parity = 0;
    RUN_PHASE(6, 4, 39, 19, 2, 1);     // s=2..7:   rows 2..40, pairs 1..19
    RUN_PHASE(6, 2, 27, 14, 8, 3);     // s=8..13:  rows 8..34, pairs 3..16
    RUN_PHASE(6, 1, 15,  8, 14, 6);    // s=14..19: rows 14..28, pairs 6..13
    // parity back to 0 -> v19 in vA

    // ---- final: q at (21,21) from v19 + qr, softmax ----
    if (t == 0) {
        const float* cur = vbase;
        float q[NACT];
        float m = -INFINITY;
        #pragma unroll
        for (int a = 0; a < NACT; a++) {
            uint64_t qv = qr2[(a >> 1) * QSTR + (21 * NPAIR + 10) * 2 + (a & 1)];
            float acc = unpack2(qv).x;             // cell (21,21) = c0 of pair 10
            #pragma unroll
            for (int ky = 0; ky < 3; ky++)
                #pragma unroll
                for (int kx = 0; kx < 3; kx++)
                    acc = fmaf(wqs[a * 18 + 9 + ky * 3 + kx],
                               cur[(20 + ky) * ST + 20 + kx], acc);
            q[a] = acc;
            m = fmaxf(m, acc);
        }
        float s = 0.f;
        #pragma unroll
        for (int a = 0; a < NACT; a++) { q[a] = expf(q[a] - m); s += q[a]; }
        float inv = 1.f / s;
        #pragma unroll
        for (int a = 0; a < NACT; a++)
            out[b * NACT + a] = q[a] * inv;
    }
}

extern "C" void kernel_launch(void* const* d_in, const int* in_sizes, int n_in,
                              void* d_out, int out_size)
{
    const float* X  = (const float*)d_in[0];   // [64,2,64,64] (batch 0 only)
    const int*   S1 = (const int*)d_in[1];     // [64]
    const int*   S2 = (const int*)d_in[2];     // [64]
    const float* Wh = (const float*)d_in[3];   // [150,2,3,3]
    const float* bh = (const float*)d_in[4];   // [150]
    const float* Wr = (const float*)d_in[5];   // [1,150,1,1]
    const float* Wq = (const float*)d_in[6];   // [8,2,3,3]
    float* out = (float*)d_out;                // [64,8]

    cudaFuncSetAttribute(vin_kernel,
                         cudaFuncAttributeMaxDynamicSharedMemorySize,
                         SMEM_BYTES);
    vin_kernel<<<64, NTH, SMEM_BYTES>>>(X, S1, S2, Wh, bh, Wr, Wq, out);
}